// round 9
// baseline (speedup 1.0000x reference)
#include <cuda_runtime.h>
#include <cuda_bf16.h>
#include <mma.h>

using namespace nvcuda;

#define BN     1024
#define NITER  50
#define EPS    0.05f
#define MMASS  0.95f
#define NB     32          // iteration blocks (32 rows + 32 cols each)
#define NT     1024        // threads per iteration block (32 warps)

// ---------------- static device scratch (no allocations allowed) ------------
__device__ __align__(16) float          g_M  [BN * BN];     // 4 MB
__device__ __align__(16) __nv_bfloat16  g_Abf[BN * BN];     // 2 MB
__device__ __align__(16) __nv_bfloat16  g_Tbf[BN * BN];     // 2 MB
__device__ __align__(16) __nv_bfloat16  g_K0 [BN * BN];     // 2 MB
__device__ __align__(16) __nv_bfloat16  g_K0T[BN * BN];     // 2 MB
__device__ __align__(16) float g_na[BN], g_nt[BN];
__device__ __align__(16) float g_maxp[128];
__device__ __align__(16) float g_sumpB[256];
__device__ __align__(16) float g_yp[BN * NB];               // [i][b]
__device__ __align__(16) float g_zp[BN * NB];               // [j][b]
__device__ __align__(16) float g_beta[BN];
__device__ __align__(16) float g_s2p[NB], g_lossp[NB];
__device__ volatile unsigned  g_flag[NB];                   // zero-init

// ---------------- warp helpers ---------------------------------------------
__device__ __forceinline__ float warp_sum(float v) {
    #pragma unroll
    for (int s = 16; s; s >>= 1) v += __shfl_xor_sync(0xffffffffu, v, s);
    return v;
}
__device__ __forceinline__ float warp_max(float v) {
    #pragma unroll
    for (int s = 16; s; s >>= 1) v = fmaxf(v, __shfl_xor_sync(0xffffffffu, v, s));
    return v;
}
__device__ __forceinline__ float red128_max(const float* p, int lane) {
    float s = fmaxf(fmaxf(__ldcg(p + lane), __ldcg(p + lane + 32)),
                    fmaxf(__ldcg(p + lane + 64), __ldcg(p + lane + 96)));
    return warp_max(s);
}

// -------- decentralized flag barrier over NB blocks -------------------------
__device__ __forceinline__ void flagbar(unsigned& eph, int b, int tid, int lane) {
    __syncthreads();
    eph++;
    if (tid == 0) {
        __threadfence();
        atomicExch((unsigned*)&g_flag[b], eph);
    }
    if (tid < 32) {
        for (;;) {
            unsigned f = g_flag[lane];
            if (__all_sync(0xffffffffu, f >= eph)) break;
        }
        __threadfence();
    }
    __syncthreads();
}

// ===================== K1: fp32 -> bf16 + row norms =========================
__global__ void __launch_bounds__(256)
k_convert(const float* __restrict__ A, const float* __restrict__ T) {
    const int b = blockIdx.x, tid = threadIdx.x;
    const int w = tid >> 5, lane = tid & 31;
    const int idx = b * 8 + w;                       // 0..2047
    int row; const float* src; __nv_bfloat16* dst; float* ndst;
    if (idx < BN) { row = idx;      src = A + (size_t)row * BN; dst = g_Abf + (size_t)row * BN; ndst = g_na; }
    else          { row = idx - BN; src = T + (size_t)row * BN; dst = g_Tbf + (size_t)row * BN; ndst = g_nt; }
    const float4* s4 = (const float4*)src;
    __nv_bfloat162* d2 = (__nv_bfloat162*)dst;
    float nrm = 0.f;
    #pragma unroll
    for (int q = 0; q < 8; q++) {
        int c4 = q * 32 + lane;
        float4 v = s4[c4];
        nrm = fmaf(v.x, v.x, fmaf(v.y, v.y, fmaf(v.z, v.z, fmaf(v.w, v.w, nrm))));
        d2[c4 * 2]     = __floats2bfloat162_rn(v.x, v.y);
        d2[c4 * 2 + 1] = __floats2bfloat162_rn(v.z, v.w);
    }
    nrm = warp_sum(nrm);
    if (lane == 0) __stcg(&ndst[row], nrm);
}

// ===================== K2: GEMM -> M (fp32) + per-block max =================
#define DT_PITCH 68
__global__ void __launch_bounds__(256)
k_gemm() {
    __shared__ float dt[128 * DT_PITCH];
    __shared__ float s_warp[8];
    const int b = blockIdx.x, tid = threadIdx.x;
    const int w = tid >> 5, lane = tid & 31;
    const int tm = (b >> 4) * 128;
    const int tn = (b & 15) * 64;
    const int wm = w >> 1, wn = w & 1;

    wmma::fragment<wmma::accumulator, 16, 16, 16, float> c[2][2];
    #pragma unroll
    for (int mi = 0; mi < 2; mi++)
        #pragma unroll
        for (int ni = 0; ni < 2; ni++) wmma::fill_fragment(c[mi][ni], 0.f);

    #pragma unroll 1
    for (int k = 0; k < BN; k += 16) {
        wmma::fragment<wmma::matrix_a, 16, 16, 16, __nv_bfloat16, wmma::row_major> af[2];
        wmma::fragment<wmma::matrix_b, 16, 16, 16, __nv_bfloat16, wmma::col_major> bf[2];
        #pragma unroll
        for (int mi = 0; mi < 2; mi++)
            wmma::load_matrix_sync(af[mi], g_Abf + (size_t)(tm + wm * 32 + mi * 16) * BN + k, BN);
        #pragma unroll
        for (int ni = 0; ni < 2; ni++)
            wmma::load_matrix_sync(bf[ni], g_Tbf + (size_t)(tn + wn * 32 + ni * 16) * BN + k, BN);
        #pragma unroll
        for (int mi = 0; mi < 2; mi++)
            #pragma unroll
            for (int ni = 0; ni < 2; ni++)
                wmma::mma_sync(c[mi][ni], af[mi], bf[ni], c[mi][ni]);
    }
    #pragma unroll
    for (int mi = 0; mi < 2; mi++)
        #pragma unroll
        for (int ni = 0; ni < 2; ni++)
            wmma::store_matrix_sync(&dt[(wm * 32 + mi * 16) * DT_PITCH + wn * 32 + ni * 16],
                                    c[mi][ni], DT_PITCH, wmma::mem_row_major);
    __syncthreads();

    float lmax = 0.f;
    #pragma unroll 1
    for (int f = tid; f < 2048; f += 256) {
        int r = f >> 4, c4 = f & 15;
        float4 d = *(const float4*)&dt[r * DT_PITCH + c4 * 4];
        float  nai = __ldcg(&g_na[tm + r]);
        float4 nt4 = __ldcg(((const float4*)g_nt) + (tn >> 2) + c4);
        float4 mv;
        mv.x = fmaxf(nai + nt4.x - 2.f * d.x, 0.f);
        mv.y = fmaxf(nai + nt4.y - 2.f * d.y, 0.f);
        mv.z = fmaxf(nai + nt4.z - 2.f * d.z, 0.f);
        mv.w = fmaxf(nai + nt4.w - 2.f * d.w, 0.f);
        lmax = fmaxf(lmax, fmaxf(fmaxf(mv.x, mv.y), fmaxf(mv.z, mv.w)));
        __stcg(((float4*)(g_M + (size_t)(tm + r) * BN + tn)) + c4, mv);
    }
    lmax = warp_max(lmax);
    if (lane == 0) s_warp[w] = lmax;
    __syncthreads();
    if (tid == 0) {
        float mx = s_warp[0];
        #pragma unroll
        for (int k = 1; k < 8; k++) mx = fmaxf(mx, s_warp[k]);
        __stcg(&g_maxp[b], mx);
    }
}

// ===================== K3: build K0 (bf16) + K0^T + sum partials ============
#define ST_PITCH 66   // EVEN pitch: (r*66 + 2*lane) always even -> 4B-aligned bf162
__global__ void __launch_bounds__(256)
k_build() {
    __shared__ __nv_bfloat16 st[64 * ST_PITCH];
    __shared__ float s_warp[8];
    __shared__ float s_max;
    const int b = blockIdx.x, tid = threadIdx.x;
    const int w = tid >> 5, lane = tid & 31;
    const int ti = b >> 4, tj = b & 15;              // 64x64 tile

    if (w == 0) {
        float mx = red128_max(g_maxp, lane);
        if (lane == 0) s_max = mx;
    }
    __syncthreads();
    const float kscale = 1.0f / (s_max * EPS);

    float psum = 0.f;
    #pragma unroll
    for (int rr = 0; rr < 8; rr++) {
        int r = w * 8 + rr;
        size_t i = (size_t)(ti * 64 + r);
        float2 m = __ldcg(((const float2*)(g_M + i * BN + tj * 64)) + lane);
        float e0 = __expf(-m.x * kscale), e1 = __expf(-m.y * kscale);
        psum += e0 + e1;
        __nv_bfloat162 p = __floats2bfloat162_rn(e0, e1);
        ((__nv_bfloat162*)(g_K0 + i * BN + tj * 64))[lane] = p;
        *(__nv_bfloat162*)&st[r * ST_PITCH + 2 * lane] = p;
    }
    psum = warp_sum(psum);
    if (lane == 0) s_warp[w] = psum;
    __syncthreads();
    if (tid == 0) {
        float s = 0.f;
        #pragma unroll
        for (int k = 0; k < 8; k++) s += s_warp[k];
        __stcg(&g_sumpB[b], s);
    }
    // transpose: K0T[tj*64+c][ti*64 + r]
    #pragma unroll
    for (int cc = 0; cc < 8; cc++) {
        int c = w * 8 + cc;
        __nv_bfloat16 a0 = st[(2 * lane)     * ST_PITCH + c];
        __nv_bfloat16 a1 = st[(2 * lane + 1) * ST_PITCH + c];
        __nv_bfloat162 p; p.x = a0; p.y = a1;
        ((__nv_bfloat162*)(g_K0T + (size_t)(tj * 64 + c) * BN + ti * 64))[lane] = p;
    }
}

// ===================== K4: iteration kernel (32 blocks x 1024 thr) ==========
__global__ void __launch_bounds__(NT, 1)
k_iter(float* __restrict__ out) {
    extern __shared__ __align__(16) char smraw[];
    __nv_bfloat16* smK0  = (__nv_bfloat16*)smraw;        // [32][1024] 64 KB (rows)
    __nv_bfloat16* smK0T = smK0 + 32 * BN;               // [32][1024] 64 KB (cols)
    float* s_bvec = (float*)(smK0T + 32 * BN);           // 4 KB (loss beta)
    __shared__ float s_alpha[32], s_beta[32], s_ct[32];

    const int b = blockIdx.x, tid = threadIdx.x;
    const int w = tid >> 5, lane = tid & 31;
    const int iown = b * 32 + w;                          // owned row == owned col
    unsigned eph = g_flag[b];

    // ---- load owned K0/K0T rows ----
    {
        const uint4* s0 = (const uint4*)(g_K0  + (size_t)iown * BN);
        const uint4* s1 = (const uint4*)(g_K0T + (size_t)iown * BN);
        uint4* d0 = (uint4*)(smK0  + w * BN);
        uint4* d1 = (uint4*)(smK0T + w * BN);
        #pragma unroll
        for (int q = 0; q < 4; q++) {
            d0[q * 32 + lane] = __ldcg(s0 + q * 32 + lane);
            d1[q * 32 + lane] = __ldcg(s1 + q * 32 + lane);
        }
    }
    // ---- g0 = m / sum(K0raw), identical in every warp ----
    float g;
    {
        float s = 0.f;
        #pragma unroll
        for (int q = 0; q < 8; q++) s += __ldcg(&g_sumpB[q * 32 + lane]);
        g = MMASS / warp_sum(s);
    }
    if (lane == 0) s_beta[w] = 1.f;
    __syncthreads();

    const float ab = 1.0f / (float)BN;
    float alpha = 1.f, u = 1.f, beta = 1.f, v = 1.f;

    #pragma unroll 1
    for (int it = 0; it < NITER; it++) {
        // ---- yp[i] = sum_{j in mine} K0T[j][i]*beta_j, i in [32w,32w+32) ----
        {
            int i = 32 * w + lane;
            float acc = 0.f;
            #pragma unroll 8
            for (int r = 0; r < 32; r++)
                acc = fmaf(__bfloat162float(smK0T[r * BN + i]), s_beta[r], acc);
            __stcg(&g_yp[(size_t)i * NB + b], acc);
        }
        flagbar(eph, b, tid, lane);

        // ---- deferred mass update + row update ----
        if (it > 0) {
            float s2 = warp_sum(__ldcg(&g_s2p[lane]));
            g *= MMASS / s2;
        }
        {
            float y = warp_sum(__ldcg(&g_yp[(size_t)iown * NB + lane]));
            float r = fminf(ab / (g * alpha * u * y), 1.f);
            alpha *= r * u;
            u = 1.f / r;
            if (lane == 0) s_alpha[w] = alpha;
        }
        __syncthreads();

        // ---- zp[j] = sum_{i in mine} K0[i][j]*alpha_i, j in [32w,32w+32) ----
        {
            int j = 32 * w + lane;
            float acc = 0.f;
            #pragma unroll 8
            for (int r = 0; r < 32; r++)
                acc = fmaf(__bfloat162float(smK0[r * BN + j]), s_alpha[r], acc);
            __stcg(&g_zp[(size_t)j * NB + b], acc);
        }
        flagbar(eph, b, tid, lane);

        // ---- col update ----
        {
            float z = warp_sum(__ldcg(&g_zp[(size_t)iown * NB + lane]));
            float t = g * v * beta * z;
            float c = fminf(ab / t, 1.f);
            beta *= c * v;
            v = 1.f / c;
            if (lane == 0) { s_ct[w] = c * t; s_beta[w] = beta; }
        }
        __syncthreads();
        if (w == 0) {
            float s = warp_sum(s_ct[lane]);
            if (lane == 0) __stcg(&g_s2p[b], s);
        }
    }

    // ---- publish beta, final mass update ----
    if (lane == 0) __stcg(&g_beta[iown], beta);
    flagbar(eph, b, tid, lane);
    {
        float s2 = warp_sum(__ldcg(&g_s2p[lane]));
        g *= MMASS / s2;
    }
    s_bvec[tid] = __ldcg(&g_beta[tid]);
    __syncthreads();

    // ---- loss: logsumexp via Taylor (pi entries <= ~1.5e-3) ----
    {
        const float ga = g * alpha;
        const __nv_bfloat16* row = smK0 + w * BN;
        float acc = 0.f;                                  // sum of exp(x)-1
        #pragma unroll 8
        for (int q = 0; q < 32; q++) {
            int j = q * 32 + lane;
            float x = ga * __bfloat162float(row[j]) * s_bvec[j];
            acc += x * (1.f + x * (0.5f + x * (1.f / 6.f)));
        }
        acc = warp_sum(acc);
        float pii = ga * __bfloat162float(row[iown]) * s_bvec[iown];
        if (lane == 0) s_ct[w] = logf(1024.f + acc) - pii;
    }
    __syncthreads();
    if (w == 0) {
        float s = warp_sum(s_ct[lane]);
        if (lane == 0) __stcg(&g_lossp[b], s);
    }
    flagbar(eph, b, tid, lane);

    if (b == 0 && w == 0) {
        float s = warp_sum(__ldcg(&g_lossp[lane]));
        if (lane == 0) out[0] = s * (1.0f / (float)BN);
    }
}

// ===========================================================================
extern "C" void kernel_launch(void* const* d_in, const int* in_sizes, int n_in,
                              void* d_out, int out_size) {
    (void)in_sizes; (void)n_in; (void)out_size;
    const float* A = (const float*)d_in[0];
    const float* T = (const float*)d_in[1];
    float* out = (float*)d_out;

    const int smem_iter = 32 * BN * 2 * 2 + BN * 4;      // 135168 B
    cudaFuncSetAttribute(k_iter, cudaFuncAttributeMaxDynamicSharedMemorySize, smem_iter);

    k_convert<<<256, 256>>>(A, T);
    k_gemm<<<128, 256>>>();
    k_build<<<256, 256>>>();
    k_iter<<<NB, NT, smem_iter>>>(out);
}

// round 10
// speedup vs baseline: 1.2786x; 1.2786x over previous
#include <cuda_runtime.h>
#include <cuda_bf16.h>
#include <mma.h>

using namespace nvcuda;

#define BN     1024
#define NITER  50
#define EPS    0.05f
#define MMASS  0.95f
#define NB     32          // iteration blocks (32 rows + 32 cols each)
#define NT     1024        // threads per iteration block (32 warps)

// ---------------- static device scratch (no allocations allowed) ------------
__device__ __align__(16) float          g_M  [BN * BN];     // 4 MB
__device__ __align__(16) __nv_bfloat16  g_Abf[BN * BN];     // 2 MB
__device__ __align__(16) __nv_bfloat16  g_Tbf[BN * BN];     // 2 MB
__device__ __align__(16) __nv_bfloat16  g_K0 [BN * BN];     // 2 MB
__device__ __align__(16) __nv_bfloat16  g_K0T[BN * BN];     // 2 MB
__device__ __align__(16) float g_na[BN], g_nt[BN];
__device__ __align__(16) float g_maxp[128];
__device__ __align__(16) float g_sumpB[256];
__device__ __align__(16) float g_yp[NB * BN];               // [src][i]  (block-major!)
__device__ __align__(16) float g_zp[NB * BN];               // [src][j]
__device__ __align__(16) float g_beta[BN];
__device__ __align__(16) float g_s2p[NB], g_lossp[NB];
__device__ volatile unsigned  g_flag[NB];                   // zero-init

// ---------------- warp helpers ---------------------------------------------
__device__ __forceinline__ float warp_sum(float v) {
    #pragma unroll
    for (int s = 16; s; s >>= 1) v += __shfl_xor_sync(0xffffffffu, v, s);
    return v;
}
__device__ __forceinline__ float warp_max(float v) {
    #pragma unroll
    for (int s = 16; s; s >>= 1) v = fmaxf(v, __shfl_xor_sync(0xffffffffu, v, s));
    return v;
}
__device__ __forceinline__ float red128_max(const float* p, int lane) {
    float s = fmaxf(fmaxf(__ldcg(p + lane), __ldcg(p + lane + 32)),
                    fmaxf(__ldcg(p + lane + 64), __ldcg(p + lane + 96)));
    return warp_max(s);
}

// -------- decentralized flag barrier over NB blocks -------------------------
__device__ __forceinline__ void flagbar(unsigned& eph, int b, int tid, int lane) {
    __syncthreads();
    eph++;
    if (tid == 0) {
        __threadfence();
        atomicExch((unsigned*)&g_flag[b], eph);
    }
    if (tid < 32) {
        for (;;) {
            unsigned f = g_flag[lane];
            if (__all_sync(0xffffffffu, f >= eph)) break;
        }
        __threadfence();
    }
    __syncthreads();
}

// ===================== K1: fp32 -> bf16 + row norms =========================
__global__ void __launch_bounds__(256)
k_convert(const float* __restrict__ A, const float* __restrict__ T) {
    const int b = blockIdx.x, tid = threadIdx.x;
    const int w = tid >> 5, lane = tid & 31;
    const int idx = b * 8 + w;                       // 0..2047
    int row; const float* src; __nv_bfloat16* dst; float* ndst;
    if (idx < BN) { row = idx;      src = A + (size_t)row * BN; dst = g_Abf + (size_t)row * BN; ndst = g_na; }
    else          { row = idx - BN; src = T + (size_t)row * BN; dst = g_Tbf + (size_t)row * BN; ndst = g_nt; }
    const float4* s4 = (const float4*)src;
    __nv_bfloat162* d2 = (__nv_bfloat162*)dst;
    float nrm = 0.f;
    #pragma unroll
    for (int q = 0; q < 8; q++) {
        int c4 = q * 32 + lane;
        float4 v = s4[c4];
        nrm = fmaf(v.x, v.x, fmaf(v.y, v.y, fmaf(v.z, v.z, fmaf(v.w, v.w, nrm))));
        d2[c4 * 2]     = __floats2bfloat162_rn(v.x, v.y);
        d2[c4 * 2 + 1] = __floats2bfloat162_rn(v.z, v.w);
    }
    nrm = warp_sum(nrm);
    if (lane == 0) __stcg(&ndst[row], nrm);
}

// ===================== K2: GEMM -> M (fp32) + per-block max =================
#define DT_PITCH 68
__global__ void __launch_bounds__(256)
k_gemm() {
    __shared__ float dt[128 * DT_PITCH];
    __shared__ float s_warp[8];
    const int b = blockIdx.x, tid = threadIdx.x;
    const int w = tid >> 5, lane = tid & 31;
    const int tm = (b >> 4) * 128;
    const int tn = (b & 15) * 64;
    const int wm = w >> 1, wn = w & 1;

    wmma::fragment<wmma::accumulator, 16, 16, 16, float> c[2][2];
    #pragma unroll
    for (int mi = 0; mi < 2; mi++)
        #pragma unroll
        for (int ni = 0; ni < 2; ni++) wmma::fill_fragment(c[mi][ni], 0.f);

    #pragma unroll 1
    for (int k = 0; k < BN; k += 16) {
        wmma::fragment<wmma::matrix_a, 16, 16, 16, __nv_bfloat16, wmma::row_major> af[2];
        wmma::fragment<wmma::matrix_b, 16, 16, 16, __nv_bfloat16, wmma::col_major> bf[2];
        #pragma unroll
        for (int mi = 0; mi < 2; mi++)
            wmma::load_matrix_sync(af[mi], g_Abf + (size_t)(tm + wm * 32 + mi * 16) * BN + k, BN);
        #pragma unroll
        for (int ni = 0; ni < 2; ni++)
            wmma::load_matrix_sync(bf[ni], g_Tbf + (size_t)(tn + wn * 32 + ni * 16) * BN + k, BN);
        #pragma unroll
        for (int mi = 0; mi < 2; mi++)
            #pragma unroll
            for (int ni = 0; ni < 2; ni++)
                wmma::mma_sync(c[mi][ni], af[mi], bf[ni], c[mi][ni]);
    }
    #pragma unroll
    for (int mi = 0; mi < 2; mi++)
        #pragma unroll
        for (int ni = 0; ni < 2; ni++)
            wmma::store_matrix_sync(&dt[(wm * 32 + mi * 16) * DT_PITCH + wn * 32 + ni * 16],
                                    c[mi][ni], DT_PITCH, wmma::mem_row_major);
    __syncthreads();

    float lmax = 0.f;
    #pragma unroll 1
    for (int f = tid; f < 2048; f += 256) {
        int r = f >> 4, c4 = f & 15;
        float4 d = *(const float4*)&dt[r * DT_PITCH + c4 * 4];
        float  nai = __ldcg(&g_na[tm + r]);
        float4 nt4 = __ldcg(((const float4*)g_nt) + (tn >> 2) + c4);
        float4 mv;
        mv.x = fmaxf(nai + nt4.x - 2.f * d.x, 0.f);
        mv.y = fmaxf(nai + nt4.y - 2.f * d.y, 0.f);
        mv.z = fmaxf(nai + nt4.z - 2.f * d.z, 0.f);
        mv.w = fmaxf(nai + nt4.w - 2.f * d.w, 0.f);
        lmax = fmaxf(lmax, fmaxf(fmaxf(mv.x, mv.y), fmaxf(mv.z, mv.w)));
        __stcg(((float4*)(g_M + (size_t)(tm + r) * BN + tn)) + c4, mv);
    }
    lmax = warp_max(lmax);
    if (lane == 0) s_warp[w] = lmax;
    __syncthreads();
    if (tid == 0) {
        float mx = s_warp[0];
        #pragma unroll
        for (int k = 1; k < 8; k++) mx = fmaxf(mx, s_warp[k]);
        __stcg(&g_maxp[b], mx);
    }
}

// ===================== K3: build K0 (bf16) + K0^T + sum partials ============
#define ST_PITCH 66   // even pitch: (r*66 + 2*lane) always even -> 4B-aligned bf162
__global__ void __launch_bounds__(256)
k_build() {
    __shared__ __nv_bfloat16 st[64 * ST_PITCH];
    __shared__ float s_warp[8];
    __shared__ float s_max;
    const int b = blockIdx.x, tid = threadIdx.x;
    const int w = tid >> 5, lane = tid & 31;
    const int ti = b >> 4, tj = b & 15;              // 64x64 tile

    if (w == 0) {
        float mx = red128_max(g_maxp, lane);
        if (lane == 0) s_max = mx;
    }
    __syncthreads();
    const float kscale = 1.0f / (s_max * EPS);

    float psum = 0.f;
    #pragma unroll
    for (int rr = 0; rr < 8; rr++) {
        int r = w * 8 + rr;
        size_t i = (size_t)(ti * 64 + r);
        float2 m = __ldcg(((const float2*)(g_M + i * BN + tj * 64)) + lane);
        float e0 = __expf(-m.x * kscale), e1 = __expf(-m.y * kscale);
        psum += e0 + e1;
        __nv_bfloat162 p = __floats2bfloat162_rn(e0, e1);
        ((__nv_bfloat162*)(g_K0 + i * BN + tj * 64))[lane] = p;
        *(__nv_bfloat162*)&st[r * ST_PITCH + 2 * lane] = p;
    }
    psum = warp_sum(psum);
    if (lane == 0) s_warp[w] = psum;
    __syncthreads();
    if (tid == 0) {
        float s = 0.f;
        #pragma unroll
        for (int k = 0; k < 8; k++) s += s_warp[k];
        __stcg(&g_sumpB[b], s);
    }
    #pragma unroll
    for (int cc = 0; cc < 8; cc++) {
        int c = w * 8 + cc;
        __nv_bfloat16 a0 = st[(2 * lane)     * ST_PITCH + c];
        __nv_bfloat16 a1 = st[(2 * lane + 1) * ST_PITCH + c];
        __nv_bfloat162 p; p.x = a0; p.y = a1;
        ((__nv_bfloat162*)(g_K0T + (size_t)(tj * 64 + c) * BN + ti * 64))[lane] = p;
    }
}

// ===================== K4: iteration kernel (32 blocks x 1024 thr) ==========
__global__ void __launch_bounds__(NT, 1)
k_iter(float* __restrict__ out) {
    extern __shared__ __align__(16) char smraw[];
    __nv_bfloat16* smK0  = (__nv_bfloat16*)smraw;        // [32][1024] rows   64 KB
    __nv_bfloat16* smK0T = smK0 + 32 * BN;               // [32][1024] cols   64 KB
    float* s_red = (float*)(smK0T + 32 * BN);            // 4 KB staging / beta vec
    __shared__ float s_alpha[32], s_beta[32], s_tmp[32];
    __shared__ float s_g;

    const int b = blockIdx.x, tid = threadIdx.x;
    const int w = tid >> 5, lane = tid & 31;
    unsigned eph = g_flag[b];

    // ---- load owned K0/K0T rows (rows & cols 32b..32b+31) ----
    {
        const uint4* s0 = (const uint4*)(g_K0  + (size_t)(b * 32 + w) * BN);
        const uint4* s1 = (const uint4*)(g_K0T + (size_t)(b * 32 + w) * BN);
        uint4* d0 = (uint4*)(smK0  + w * BN);
        uint4* d1 = (uint4*)(smK0T + w * BN);
        #pragma unroll
        for (int q = 0; q < 4; q++) {
            d0[q * 32 + lane] = __ldcg(s0 + q * 32 + lane);
            d1[q * 32 + lane] = __ldcg(s1 + q * 32 + lane);
        }
    }

    // ---- warp-0-resident scalar state: row/col 32b+lane ----
    float g = 0.f, alpha = 1.f, u = 1.f, beta = 1.f, v = 1.f;
    if (w == 0) {
        float s = 0.f;
        #pragma unroll
        for (int q = 0; q < 8; q++) s += __ldcg(&g_sumpB[q * 32 + lane]);
        g = MMASS / warp_sum(s);
        s_beta[lane] = 1.f;
        s_alpha[lane] = 1.f;
    }
    __syncthreads();

    const float ab = 1.0f / (float)BN;
    const int half = tid >> 9;              // 0 or 1
    const int p    = tid & 511;             // bf162 pair index 0..511

    #pragma unroll 1
    for (int it = 0; it < NITER; it++) {
        // ---- yp partial: yp_b[i] = sum_{j in own32} K0T[j][i]*beta_j ------
        if (half == 0) {
            const __nv_bfloat162* kt = (const __nv_bfloat162*)smK0T;
            float ax = 0.f, ay = 0.f;
            #pragma unroll 8
            for (int r = 0; r < 32; r++) {
                float2 k2 = __bfloat1622float2(kt[r * 512 + p]);
                float fb = s_beta[r];
                ax = fmaf(k2.x, fb, ax);
                ay = fmaf(k2.y, fb, ay);
            }
            float2 o; o.x = ax; o.y = ay;
            __stcg(((float2*)(g_yp + (size_t)b * BN)) + p, o);   // contiguous 4KB
        }
        flagbar(eph, b, tid, lane);

        // ---- stage: warp w reads source w's slice (coalesced 128B) --------
        s_red[w * 32 + lane] = __ldcg(&g_yp[(size_t)w * BN + b * 32 + lane]);
        if (w == 31 && it > 0) {
            float s2 = warp_sum(__ldcg(&g_s2p[lane]));
            if (lane == 0) s_g = s2;
        }
        __syncthreads();

        // ---- warp 0: reduce + mass + row update ---------------------------
        if (w == 0) {
            float y = 0.f;
            #pragma unroll 8
            for (int src = 0; src < 32; src++) y += s_red[src * 32 + lane];
            if (it > 0) g *= MMASS / s_g;
            float r = fminf(ab / (g * alpha * u * y), 1.f);
            alpha *= r * u;
            u = 1.f / r;
            s_alpha[lane] = alpha;
        }
        __syncthreads();

        // ---- zp partial: zp_b[j] = sum_{i in own32} K0[i][j]*alpha_i ------
        if (half == 0) {
            const __nv_bfloat162* kk = (const __nv_bfloat162*)smK0;
            float ax = 0.f, ay = 0.f;
            #pragma unroll 8
            for (int r = 0; r < 32; r++) {
                float2 k2 = __bfloat1622float2(kk[r * 512 + p]);
                float fa = s_alpha[r];
                ax = fmaf(k2.x, fa, ax);
                ay = fmaf(k2.y, fa, ay);
            }
            float2 o; o.x = ax; o.y = ay;
            __stcg(((float2*)(g_zp + (size_t)b * BN)) + p, o);
        }
        flagbar(eph, b, tid, lane);

        // ---- stage + warp 0 col update ------------------------------------
        s_red[w * 32 + lane] = __ldcg(&g_zp[(size_t)w * BN + b * 32 + lane]);
        __syncthreads();
        if (w == 0) {
            float z = 0.f;
            #pragma unroll 8
            for (int src = 0; src < 32; src++) z += s_red[src * 32 + lane];
            float t = g * v * beta * z;                  // colsum(K1p)
            float c = fminf(ab / t, 1.f);
            beta *= c * v;
            v = 1.f / c;
            s_beta[lane] = beta;
            float s2p = warp_sum(c * t);                 // colsum(K2) partial
            if (lane == 0) __stcg(&g_s2p[b], s2p);
        }
        __syncthreads();
    }

    // ---- publish beta, final mass update ----
    if (w == 0) __stcg(&g_beta[b * 32 + lane], beta);
    flagbar(eph, b, tid, lane);
    if (w == 0) {
        float s2 = warp_sum(__ldcg(&g_s2p[lane]));
        if (lane == 0) s_g = g * (MMASS / s2);           // final g
    }
    s_red[tid] = __ldcg(&g_beta[tid]);                   // full beta vector
    __syncthreads();

    // ---- loss: logsumexp via Taylor (pi entries <= ~1.5e-3) ----
    {
        const int iown = b * 32 + w;
        const float ga = s_g * s_alpha[w];
        const __nv_bfloat16* row = smK0 + w * BN;
        float acc = 0.f;                                 // sum of exp(x)-1
        #pragma unroll 8
        for (int q = 0; q < 32; q++) {
            int j = q * 32 + lane;
            float x = ga * __bfloat162float(row[j]) * s_red[j];
            acc += x * (1.f + x * (0.5f + x * (1.f / 6.f)));
        }
        acc = warp_sum(acc);
        float pii = ga * __bfloat162float(row[iown]) * s_red[iown];
        if (lane == 0) s_tmp[w] = logf(1024.f + acc) - pii;
    }
    __syncthreads();
    if (w == 0) {
        float s = warp_sum(s_tmp[lane]);
        if (lane == 0) __stcg(&g_lossp[b], s);
    }
    flagbar(eph, b, tid, lane);

    if (b == 0 && w == 0) {
        float s = warp_sum(__ldcg(&g_lossp[lane]));
        if (lane == 0) out[0] = s * (1.0f / (float)BN);
    }
}

// ===========================================================================
extern "C" void kernel_launch(void* const* d_in, const int* in_sizes, int n_in,
                              void* d_out, int out_size) {
    (void)in_sizes; (void)n_in; (void)out_size;
    const float* A = (const float*)d_in[0];
    const float* T = (const float*)d_in[1];
    float* out = (float*)d_out;

    const int smem_iter = 32 * BN * 2 * 2 + BN * 4;      // 135168 B
    cudaFuncSetAttribute(k_iter, cudaFuncAttributeMaxDynamicSharedMemorySize, smem_iter);

    k_convert<<<256, 256>>>(A, T);
    k_gemm<<<128, 256>>>();
    k_build<<<256, 256>>>();
    k_iter<<<NB, NT, smem_iter>>>(out);
}